// round 4
// baseline (speedup 1.0000x reference)
#include <cuda_runtime.h>

#define BG 128
#define NN 128
#define MM 16
#define KK 8
#define HM 16
#define DP 64
#define NE 262144
#define NSUM (BG*NN)   // 16384
#define CAP 96

typedef unsigned long long u64;

// ---------------- scratch (static device globals; no runtime alloc) --------
// g_hbn: per node [c][m]  (c=0..15 channel, m fast)   -> 16 MB
// g_h1 : per node [d][m]  (d=0..63, m fast)           -> 64 MB
__device__ float g_hbn[NSUM*256];
__device__ float g_h1 [NSUM*1024];
__device__ int   g_cnt [NSUM];
__device__ int   g_adj [NSUM*CAP];   // padded adjacency, 6 MB

// ---------------- f32x2 helpers (Blackwell packed fp32) --------------------
__device__ __forceinline__ u64 ffma2(u64 a, u64 b, u64 c) {
    u64 d; asm("fma.rn.f32x2 %0,%1,%2,%3;" : "=l"(d) : "l"(a), "l"(b), "l"(c));
    return d;
}
__device__ __forceinline__ u64 fadd2(u64 a, u64 b) {
    u64 d; asm("add.rn.f32x2 %0,%1,%2;" : "=l"(d) : "l"(a), "l"(b));
    return d;
}
__device__ __forceinline__ u64 pack2(float x, float y) {
    u64 r; asm("mov.b64 %0,{%1,%2};" : "=l"(r) : "f"(x), "f"(y));
    return r;
}
__device__ __forceinline__ float2 unpk(u64 v) {
    float2 r; asm("mov.b64 {%0,%1},%2;" : "=f"(r.x), "=f"(r.y) : "l"(v));
    return r;
}

// ================= Kernel A: poly filter + MLP + BatchNorm + ReLU =========
// 1 block/graph, 512 threads. Output written TRANSPOSED per node: [c][m]
// (m is the fast thread index -> the transposed store is coalesced, 64B/half-warp).
__global__ __launch_bounds__(512) void kA(
    const float* __restrict__ lap, const float* __restrict__ W0,
    const float* __restrict__ mlpW, const float* __restrict__ mlpb,
    const float* __restrict__ bng,  const float* __restrict__ bnb)
{
    extern __shared__ float sm[];
    float* lap_s = sm;                    // 128*132
    float* w_s   = lap_s + 128*132;       // 2*2064
    float* mw_s  = w_s + 2*2064;          // 128
    float* redS  = mw_s + 128;            // 256
    float* redQ  = redS + 256;            // 256
    float* a_s   = redQ + 256;            // 16
    float* c_s   = a_s + 16;              // 16

    const int b = blockIdx.x, tid = threadIdx.x;
    const float* lb = lap + (size_t)b*NN*NN;
    for (int q = tid; q < NN*NN/4; q += 512) {
        int n = q >> 5, j4 = (q & 31) << 2;
        *(float4*)(lap_s + n*132 + j4) = *(const float4*)(lb + n*NN + j4);
    }
    if (tid < KK*HM) mw_s[tid] = mlpW[tid];

    const int m = tid & 15, g = tid >> 4, n0 = g << 2;

    float hacc[4][16];
    #pragma unroll
    for (int r = 0; r < 4; r++)
        #pragma unroll
        for (int c = 0; c < 16; c++) hacc[r][c] = 0.f;

    float wv[4];
    #pragma unroll
    for (int r = 0; r < 4; r++) {
        wv[r] = W0[(size_t)b*NN*MM + (n0+r)*MM + m];
        w_s[m*129 + n0 + r] = wv[r];
    }
    __syncthreads();
    #pragma unroll
    for (int r = 0; r < 4; r++)
        #pragma unroll
        for (int c = 0; c < 16; c++) hacc[r][c] += wv[r]*mw_s[c];

    int cur = 0;
    for (int k = 1; k < KK; k++) {
        float acc0=0.f, acc1=0.f, acc2=0.f, acc3=0.f;
        const float* wr = w_s + cur*2064 + m*129;
        const float* l0 = lap_s + (n0+0)*132;
        const float* l1 = lap_s + (n0+1)*132;
        const float* l2 = lap_s + (n0+2)*132;
        const float* l3 = lap_s + (n0+3)*132;
        #pragma unroll 8
        for (int j = 0; j < NN; j += 4) {
            float w0=wr[j], w1=wr[j+1], w2=wr[j+2], w3=wr[j+3];
            float4 a  = *(const float4*)(l0+j);
            float4 b4 = *(const float4*)(l1+j);
            float4 c4 = *(const float4*)(l2+j);
            float4 d4 = *(const float4*)(l3+j);
            acc0 += a.x *w0 + a.y *w1 + a.z *w2 + a.w *w3;
            acc1 += b4.x*w0 + b4.y*w1 + b4.z*w2 + b4.w*w3;
            acc2 += c4.x*w0 + c4.y*w1 + c4.z*w2 + c4.w*w3;
            acc3 += d4.x*w0 + d4.y*w1 + d4.z*w2 + d4.w*w3;
        }
        float* wn = w_s + (cur^1)*2064 + m*129;
        wn[n0]=acc0; wn[n0+1]=acc1; wn[n0+2]=acc2; wn[n0+3]=acc3;
        const float* mw = mw_s + k*16;
        float av[4] = {acc0, acc1, acc2, acc3};
        #pragma unroll
        for (int r = 0; r < 4; r++)
            #pragma unroll
            for (int c = 0; c < 16; c++) hacc[r][c] += av[r]*mw[c];
        __syncthreads();
        cur ^= 1;
    }
    #pragma unroll
    for (int c = 0; c < 16; c++) {
        float bb = mlpb[c];
        #pragma unroll
        for (int r = 0; r < 4; r++) hacc[r][c] += bb;
    }
    float s[16], q[16];
    #pragma unroll
    for (int c = 0; c < 16; c++) {
        s[c] = hacc[0][c]+hacc[1][c]+hacc[2][c]+hacc[3][c];
        q[c] = hacc[0][c]*hacc[0][c]+hacc[1][c]*hacc[1][c]
             + hacc[2][c]*hacc[2][c]+hacc[3][c]*hacc[3][c];
    }
    #pragma unroll
    for (int o = 16; o > 0; o >>= 1) {
        #pragma unroll
        for (int c = 0; c < 16; c++) {
            s[c] += __shfl_xor_sync(0xffffffffu, s[c], o);
            q[c] += __shfl_xor_sync(0xffffffffu, q[c], o);
        }
    }
    const int warp = tid >> 5, lane = tid & 31;
    if (lane == 0) {
        #pragma unroll
        for (int c = 0; c < 16; c++) { redS[warp*16+c]=s[c]; redQ[warp*16+c]=q[c]; }
    }
    __syncthreads();
    if (tid < 16) {
        float S=0.f, Q=0.f;
        #pragma unroll
        for (int w = 0; w < 16; w++) { S += redS[w*16+tid]; Q += redQ[w*16+tid]; }
        float mean = S * (1.0f/2048.0f);
        float var  = Q * (1.0f/2048.0f) - mean*mean;
        float rstd = rsqrtf(var + 1e-5f);
        float gch  = bng[tid];
        a_s[tid] = rstd * gch;
        c_s[tid] = bnb[tid] - mean * rstd * gch;
    }
    __syncthreads();
    // transposed store [c][m]; lanes with same (r,c) differ only in m -> coalesced
    #pragma unroll
    for (int r = 0; r < 4; r++) {
        float* dst = g_hbn + ((size_t)(b*NN + n0 + r))*256 + m;
        #pragma unroll
        for (int c = 0; c < 16; c++)
            dst[c*16] = fmaxf(hacc[r][c]*a_s[c] + c_s[c], 0.f);
    }
}

// ================= padded-bucket adjacency (no scan) =======================
__global__ void kZero() {
    int i = blockIdx.x*blockDim.x + threadIdx.x;
    if (i < NSUM) g_cnt[i] = 0;
}
__global__ void kFill(const int* __restrict__ ei) {
    int i = blockIdx.x*blockDim.x + threadIdx.x;
    if (i < NE) {
        int src = ei[i], dst = ei[NE + i];
        int p = atomicAdd(&g_cnt[dst], 1);
        if (p < CAP) g_adj[dst*CAP + p] = src;
    }
}

// ================= Kernel C: GIN layer 1 (agg + 2 GEMMs, f32x2) ============
// 4 nodes/block, 128 thr/node. Outputs packed over m-pairs; weights duplicated
// (w,w) in smem so fma.rn.f32x2 needs no per-iteration packing.
__global__ __launch_bounds__(512) void kGin1(
    const float* __restrict__ eps1p,
    const float* __restrict__ W1a, const float* __restrict__ b1a,
    const float* __restrict__ W1b, const float* __restrict__ b1b)
{
    extern __shared__ u64 sd1[];
    u64* Wa2 = sd1;              // 16*64 = 1024
    u64* Wb2 = Wa2 + 1024;       // 64*64 = 4096
    u64* bi2 = Wb2 + 4096;       // 128 (ba dup | bb dup)
    float* buf = (float*)(bi2 + 128);   // 4 * 1152 floats

    const int tid = threadIdx.x;
    for (int i = tid; i < 1024; i += 512) { float w = W1a[i]; Wa2[i] = pack2(w, w); }
    for (int i = tid; i < 4096; i += 512) { float w = W1b[i]; Wb2[i] = pack2(w, w); }
    if (tid < 64) { bi2[tid] = pack2(b1a[tid], b1a[tid]); bi2[64+tid] = pack2(b1b[tid], b1b[tid]); }

    const int g = tid >> 7, lt = tid & 127;
    const int v = blockIdx.x*4 + g;
    float* zb = buf + g*1152;
    const float eps = 1.0f + eps1p[0];

    // aggregation over in-edges; hbn layout [c][m] -> thread owns one m-pair of one c
    u64 acc = 0ull;
    const int cnt = min(g_cnt[v], CAP);
    const int* adj = g_adj + v*CAP;
    for (int e = 0; e < cnt; e++) {
        acc = fadd2(acc, *(const u64*)(g_hbn + (size_t)adj[e]*256 + lt*2));
    }
    {
        u64 ep = pack2(eps, eps);
        u64 hv = *(const u64*)(g_hbn + (size_t)v*256 + lt*2);
        *(u64*)(zb + lt*2) = ffma2(ep, hv, acc);     // zT[c][m], conflict-free
    }
    __syncthreads();

    const int dq = lt & 15, mg = lt >> 4, mm = mg*2, d0 = dq*4;
    u64 C0, C1, C2, C3;
    {   // GEMM1: out[m][d] = sum_c z[m][c]*Wa[c][d], packed over (m0,m1)
        C0 = bi2[d0]; C1 = bi2[d0+1]; C2 = bi2[d0+2]; C3 = bi2[d0+3];
        #pragma unroll
        for (int c = 0; c < 16; c++) {
            u64 xp = *(const u64*)(zb + c*16 + mm);
            ulonglong2 w01 = *(const ulonglong2*)(Wa2 + c*64 + d0);
            ulonglong2 w23 = *(const ulonglong2*)(Wa2 + c*64 + d0 + 2);
            C0 = ffma2(xp, w01.x, C0); C1 = ffma2(xp, w01.y, C1);
            C2 = ffma2(xp, w23.x, C2); C3 = ffma2(xp, w23.y, C3);
        }
    }
    float tl[4], th[4];
    { float2 t;
      t=unpk(C0); tl[0]=fmaxf(t.x,0.f); th[0]=fmaxf(t.y,0.f);
      t=unpk(C1); tl[1]=fmaxf(t.x,0.f); th[1]=fmaxf(t.y,0.f);
      t=unpk(C2); tl[2]=fmaxf(t.x,0.f); th[2]=fmaxf(t.y,0.f);
      t=unpk(C3); tl[3]=fmaxf(t.x,0.f); th[3]=fmaxf(t.y,0.f); }
    __syncthreads();
    #pragma unroll
    for (int j = 0; j < 4; j++)
        *(u64*)(zb + (d0+j)*18 + mm) = pack2(tl[j], th[j]);   // tT stride 18
    __syncthreads();
    {   // GEMM2: [16,64]@[64,64]
        C0 = bi2[64+d0]; C1 = bi2[64+d0+1]; C2 = bi2[64+d0+2]; C3 = bi2[64+d0+3];
        #pragma unroll 8
        for (int c = 0; c < 64; c++) {
            u64 xp = *(const u64*)(zb + c*18 + mm);
            ulonglong2 w01 = *(const ulonglong2*)(Wb2 + c*64 + d0);
            ulonglong2 w23 = *(const ulonglong2*)(Wb2 + c*64 + d0 + 2);
            C0 = ffma2(xp, w01.x, C0); C1 = ffma2(xp, w01.y, C1);
            C2 = ffma2(xp, w23.x, C2); C3 = ffma2(xp, w23.y, C3);
        }
    }
    { float2 t;
      t=unpk(C0); tl[0]=fmaxf(t.x,0.f); th[0]=fmaxf(t.y,0.f);
      t=unpk(C1); tl[1]=fmaxf(t.x,0.f); th[1]=fmaxf(t.y,0.f);
      t=unpk(C2); tl[2]=fmaxf(t.x,0.f); th[2]=fmaxf(t.y,0.f);
      t=unpk(C3); tl[3]=fmaxf(t.x,0.f); th[3]=fmaxf(t.y,0.f); }
    __syncthreads();
    #pragma unroll
    for (int j = 0; j < 4; j++)
        *(u64*)(zb + (d0+j)*18 + mm) = pack2(tl[j], th[j]);   // stage h1T
    __syncthreads();
    // coalesced copy to g_h1 (layout [d][m] per node)
    {
        const int d = lt >> 1, m0 = (lt & 1) * 8;
        const float* sp = zb + d*18 + m0;
        u64 q0 = *(const u64*)(sp + 0), q1 = *(const u64*)(sp + 2);
        u64 q2 = *(const u64*)(sp + 4), q3 = *(const u64*)(sp + 6);
        ulonglong2* op = (ulonglong2*)(g_h1 + (size_t)v*1024 + lt*8);
        op[0] = make_ulonglong2(q0, q1);
        op[1] = make_ulonglong2(q2, q3);
    }
}

// ================= Kernel D: GIN layer 2 + sample-sum (f32x2) ==============
__global__ __launch_bounds__(512) void kGin2(
    const float* __restrict__ eps2p,
    const float* __restrict__ W2a, const float* __restrict__ b2a,
    const float* __restrict__ W2b, const float* __restrict__ b2b,
    float* __restrict__ out)
{
    extern __shared__ u64 sd2[];
    u64* Wa2 = sd2;              // 4096
    u64* Wb2 = Wa2 + 4096;       // 4096
    u64* bi2 = Wb2 + 4096;       // 128
    float* buf = (float*)(bi2 + 128);   // 4 * 1152 floats

    const int tid = threadIdx.x;
    for (int i = tid; i < 4096; i += 512) {
        float wa = W2a[i], wb = W2b[i];
        Wa2[i] = pack2(wa, wa); Wb2[i] = pack2(wb, wb);
    }
    if (tid < 64) { bi2[tid] = pack2(b2a[tid], b2a[tid]); bi2[64+tid] = pack2(b2b[tid], b2b[tid]); }

    const int g = tid >> 7, lt = tid & 127;
    const int v = blockIdx.x*4 + g;
    float* zb = buf + g*1152;
    const float eps = 1.0f + eps2p[0];

    // aggregation: h1 layout [d][m]; thread owns 8 contiguous floats (4 m-pairs)
    u64 a0 = 0ull, a1 = 0ull, a2 = 0ull, a3 = 0ull;
    const int cnt = min(g_cnt[v], CAP);
    const int* adj = g_adj + v*CAP;
    #pragma unroll 2
    for (int e = 0; e < cnt; e++) {
        const ulonglong2* p = (const ulonglong2*)(g_h1 + (size_t)adj[e]*1024 + lt*8);
        ulonglong2 x = p[0], y = p[1];
        a0 = fadd2(a0, x.x); a1 = fadd2(a1, x.y);
        a2 = fadd2(a2, y.x); a3 = fadd2(a3, y.y);
    }
    {
        u64 ep = pack2(eps, eps);
        const ulonglong2* hp = (const ulonglong2*)(g_h1 + (size_t)v*1024 + lt*8);
        ulonglong2 hx = hp[0], hy = hp[1];
        ulonglong2* zp = (ulonglong2*)(zb + lt*8);   // zT[d][m], STS.128 conflict-free
        zp[0] = make_ulonglong2(ffma2(ep, hx.x, a0), ffma2(ep, hx.y, a1));
        zp[1] = make_ulonglong2(ffma2(ep, hy.x, a2), ffma2(ep, hy.y, a3));
    }
    __syncthreads();

    const int dq = lt & 15, mg = lt >> 4, mm = mg*2, d0 = dq*4;
    u64 C0, C1, C2, C3;
    {   // GEMM1: [16,64]@[64,64] packed over m-pairs
        C0 = bi2[d0]; C1 = bi2[d0+1]; C2 = bi2[d0+2]; C3 = bi2[d0+3];
        #pragma unroll 8
        for (int c = 0; c < 64; c++) {
            u64 xp = *(const u64*)(zb + c*16 + mm);
            ulonglong2 w01 = *(const ulonglong2*)(Wa2 + c*64 + d0);
            ulonglong2 w23 = *(const ulonglong2*)(Wa2 + c*64 + d0 + 2);
            C0 = ffma2(xp, w01.x, C0); C1 = ffma2(xp, w01.y, C1);
            C2 = ffma2(xp, w23.x, C2); C3 = ffma2(xp, w23.y, C3);
        }
    }
    float tl[4], th[4];
    { float2 t;
      t=unpk(C0); tl[0]=fmaxf(t.x,0.f); th[0]=fmaxf(t.y,0.f);
      t=unpk(C1); tl[1]=fmaxf(t.x,0.f); th[1]=fmaxf(t.y,0.f);
      t=unpk(C2); tl[2]=fmaxf(t.x,0.f); th[2]=fmaxf(t.y,0.f);
      t=unpk(C3); tl[3]=fmaxf(t.x,0.f); th[3]=fmaxf(t.y,0.f); }
    __syncthreads();
    #pragma unroll
    for (int j = 0; j < 4; j++)
        *(u64*)(zb + (d0+j)*18 + mm) = pack2(tl[j], th[j]);   // tT stride 18
    __syncthreads();
    {   // GEMM2
        C0 = bi2[64+d0]; C1 = bi2[64+d0+1]; C2 = bi2[64+d0+2]; C3 = bi2[64+d0+3];
        #pragma unroll 8
        for (int c = 0; c < 64; c++) {
            u64 xp = *(const u64*)(zb + c*18 + mm);
            ulonglong2 w01 = *(const ulonglong2*)(Wb2 + c*64 + d0);
            ulonglong2 w23 = *(const ulonglong2*)(Wb2 + c*64 + d0 + 2);
            C0 = ffma2(xp, w01.x, C0); C1 = ffma2(xp, w01.y, C1);
            C2 = ffma2(xp, w23.x, C2); C3 = ffma2(xp, w23.y, C3);
        }
    }
    float P[4];
    { float2 t;
      t=unpk(C0); P[0]=fmaxf(t.x,0.f)+fmaxf(t.y,0.f);
      t=unpk(C1); P[1]=fmaxf(t.x,0.f)+fmaxf(t.y,0.f);
      t=unpk(C2); P[2]=fmaxf(t.x,0.f)+fmaxf(t.y,0.f);
      t=unpk(C3); P[3]=fmaxf(t.x,0.f)+fmaxf(t.y,0.f); }
    __syncthreads();
    #pragma unroll
    for (int j = 0; j < 4; j++) zb[mg*64 + d0 + j] = P[j];   // partial m-sums
    __syncthreads();
    if (lt < 64) {
        float ssum = 0.f;
        #pragma unroll
        for (int r = 0; r < 8; r++) ssum += zb[r*64 + lt];
        out[(size_t)v*64 + lt] = ssum;
    }
}

// ================= launch ==================================================
extern "C" void kernel_launch(void* const* d_in, const int* in_sizes, int n_in,
                              void* d_out, int out_size)
{
    const float* lap  = (const float*)d_in[0];
    const float* W0   = (const float*)d_in[1];
    const float* mlpW = (const float*)d_in[2];
    const float* mlpb = (const float*)d_in[3];
    const float* bng  = (const float*)d_in[4];
    const float* bnb  = (const float*)d_in[5];
    const float* eps1 = (const float*)d_in[6];
    const float* W1a  = (const float*)d_in[7];
    const float* b1a  = (const float*)d_in[8];
    const float* W1b  = (const float*)d_in[9];
    const float* b1b  = (const float*)d_in[10];
    const float* eps2 = (const float*)d_in[11];
    const float* W2a  = (const float*)d_in[12];
    const float* b2a  = (const float*)d_in[13];
    const float* W2b  = (const float*)d_in[14];
    const float* b2b  = (const float*)d_in[15];
    const int*   ei   = (const int*)d_in[16];
    float* out = (float*)d_out;

    const int SMEM_A  = 21696 * 4;                       // 86784 B
    const int SMEM_G1 = (1024+4096+128)*8 + 4*1152*4;    // 60416 B
    const int SMEM_G2 = (4096+4096+128)*8 + 4*1152*4;    // 84992 B
    cudaFuncSetAttribute(kA,    cudaFuncAttributeMaxDynamicSharedMemorySize, SMEM_A);
    cudaFuncSetAttribute(kGin1, cudaFuncAttributeMaxDynamicSharedMemorySize, SMEM_G1);
    cudaFuncSetAttribute(kGin2, cudaFuncAttributeMaxDynamicSharedMemorySize, SMEM_G2);

    kZero<<<NSUM/256, 256>>>();
    kFill<<<NE/256, 256>>>(ei);
    kA   <<<BG, 512, SMEM_A>>>(lap, W0, mlpW, mlpb, bng, bnb);
    kGin1<<<NSUM/4, 512, SMEM_G1>>>(eps1, W1a, b1a, W1b, b1b);
    kGin2<<<NSUM/4, 512, SMEM_G2>>>(eps2, W2a, b2a, W2b, b2b, out);
}

// round 6
// speedup vs baseline: 1.3551x; 1.3551x over previous
#include <cuda_runtime.h>

#define BG 128
#define NN 128
#define NE 262144
#define NSUM (BG*NN)   // 16384
#define CAP 96

typedef unsigned long long u64;

// ---------------- scratch (static device globals; no runtime alloc) --------
// g_hbn: per node [c][m]  (c=0..15, m fast)  -> 16 MB
// g_h1 : per node [d][m]  (d=0..63, m fast)  -> 64 MB
__device__ float g_hbn[NSUM*256];
__device__ float g_h1 [NSUM*1024];
__device__ int   g_cnt [NSUM];
__device__ int   g_adj [NSUM*CAP];

// ---------------- f32x2 helpers -------------------------------------------
__device__ __forceinline__ u64 ffma2(u64 a, u64 b, u64 c) {
    u64 d; asm("fma.rn.f32x2 %0,%1,%2,%3;" : "=l"(d) : "l"(a), "l"(b), "l"(c));
    return d;
}
__device__ __forceinline__ u64 fadd2(u64 a, u64 b) {
    u64 d; asm("add.rn.f32x2 %0,%1,%2;" : "=l"(d) : "l"(a), "l"(b));
    return d;
}
__device__ __forceinline__ u64 pack2(float x, float y) {
    u64 r; asm("mov.b64 %0,{%1,%2};" : "=l"(r) : "f"(x), "f"(y));
    return r;
}
__device__ __forceinline__ float2 unpk(u64 v) {
    float2 r; asm("mov.b64 {%0,%1},%2;" : "=f"(r.x), "=f"(r.y) : "l"(v));
    return r;
}
// weight smem slot for (reduction row c, output d): u64 idx = c*64 + j*16 + dq*2 + e
__device__ __forceinline__ int wIdx(int c, int d) {
    int dq = d >> 3, rr = d & 7;
    return c*64 + (rr >> 1)*16 + dq*2 + (rr & 1);
}
// permuted buffer row for reduction index c (GEMM2 staging)
__device__ __forceinline__ int prow(int c) { return ((c & 7) << 3) | (c >> 3); }

// ================= Kernel A: poly filter + MLP + BatchNorm + ReLU =========
__global__ __launch_bounds__(512) void kA(
    const float* __restrict__ lap, const float* __restrict__ W0,
    const float* __restrict__ mlpW, const float* __restrict__ mlpb,
    const float* __restrict__ bng,  const float* __restrict__ bnb)
{
    extern __shared__ float sm[];
    float* lap_s = sm;                    // 128*132
    float* w_s   = lap_s + 128*132;       // 2*2064
    float* mw_s  = w_s + 2*2064;          // 128
    float* redS  = mw_s + 128;            // 256
    float* redQ  = redS + 256;            // 256
    float* a_s   = redQ + 256;            // 16
    float* c_s   = a_s + 16;              // 16

    const int b = blockIdx.x, tid = threadIdx.x;
    const float* lb = lap + (size_t)b*NN*NN;
    for (int q = tid; q < NN*NN/4; q += 512) {
        int n = q >> 5, j4 = (q & 31) << 2;
        *(float4*)(lap_s + n*132 + j4) = *(const float4*)(lb + n*NN + j4);
    }
    if (tid < 128) mw_s[tid] = mlpW[tid];

    const int m = tid & 15, g = tid >> 4, n0 = g << 2;

    float hacc[4][16];
    #pragma unroll
    for (int r = 0; r < 4; r++)
        #pragma unroll
        for (int c = 0; c < 16; c++) hacc[r][c] = 0.f;

    float wv[4];
    #pragma unroll
    for (int r = 0; r < 4; r++) {
        wv[r] = W0[(size_t)b*NN*16 + (n0+r)*16 + m];
        w_s[m*129 + n0 + r] = wv[r];
    }
    __syncthreads();
    #pragma unroll
    for (int r = 0; r < 4; r++)
        #pragma unroll
        for (int c = 0; c < 16; c++) hacc[r][c] += wv[r]*mw_s[c];

    int cur = 0;
    for (int k = 1; k < 8; k++) {
        float acc0=0.f, acc1=0.f, acc2=0.f, acc3=0.f;
        const float* wr = w_s + cur*2064 + m*129;
        const float* l0 = lap_s + (n0+0)*132;
        const float* l1 = lap_s + (n0+1)*132;
        const float* l2 = lap_s + (n0+2)*132;
        const float* l3 = lap_s + (n0+3)*132;
        #pragma unroll 8
        for (int j = 0; j < NN; j += 4) {
            float w0=wr[j], w1=wr[j+1], w2=wr[j+2], w3=wr[j+3];
            float4 a  = *(const float4*)(l0+j);
            float4 b4 = *(const float4*)(l1+j);
            float4 c4 = *(const float4*)(l2+j);
            float4 d4 = *(const float4*)(l3+j);
            acc0 += a.x *w0 + a.y *w1 + a.z *w2 + a.w *w3;
            acc1 += b4.x*w0 + b4.y*w1 + b4.z*w2 + b4.w*w3;
            acc2 += c4.x*w0 + c4.y*w1 + c4.z*w2 + c4.w*w3;
            acc3 += d4.x*w0 + d4.y*w1 + d4.z*w2 + d4.w*w3;
        }
        float* wn = w_s + (cur^1)*2064 + m*129;
        wn[n0]=acc0; wn[n0+1]=acc1; wn[n0+2]=acc2; wn[n0+3]=acc3;
        const float* mw = mw_s + k*16;
        float av[4] = {acc0, acc1, acc2, acc3};
        #pragma unroll
        for (int r = 0; r < 4; r++)
            #pragma unroll
            for (int c = 0; c < 16; c++) hacc[r][c] += av[r]*mw[c];
        __syncthreads();
        cur ^= 1;
    }
    #pragma unroll
    for (int c = 0; c < 16; c++) {
        float bb = mlpb[c];
        #pragma unroll
        for (int r = 0; r < 4; r++) hacc[r][c] += bb;
    }
    float s[16], q[16];
    #pragma unroll
    for (int c = 0; c < 16; c++) {
        s[c] = hacc[0][c]+hacc[1][c]+hacc[2][c]+hacc[3][c];
        q[c] = hacc[0][c]*hacc[0][c]+hacc[1][c]*hacc[1][c]
             + hacc[2][c]*hacc[2][c]+hacc[3][c]*hacc[3][c];
    }
    #pragma unroll
    for (int o = 16; o > 0; o >>= 1) {
        #pragma unroll
        for (int c = 0; c < 16; c++) {
            s[c] += __shfl_xor_sync(0xffffffffu, s[c], o);
            q[c] += __shfl_xor_sync(0xffffffffu, q[c], o);
        }
    }
    const int warp = tid >> 5, lane = tid & 31;
    if (lane == 0) {
        #pragma unroll
        for (int c = 0; c < 16; c++) { redS[warp*16+c]=s[c]; redQ[warp*16+c]=q[c]; }
    }
    __syncthreads();
    if (tid < 16) {
        float S=0.f, Q=0.f;
        #pragma unroll
        for (int w = 0; w < 16; w++) { S += redS[w*16+tid]; Q += redQ[w*16+tid]; }
        float mean = S * (1.0f/2048.0f);
        float var  = Q * (1.0f/2048.0f) - mean*mean;
        float rstd = rsqrtf(var + 1e-5f);
        float gch  = bng[tid];
        a_s[tid] = rstd * gch;
        c_s[tid] = bnb[tid] - mean * rstd * gch;
    }
    __syncthreads();
    #pragma unroll
    for (int r = 0; r < 4; r++) {
        float* dst = g_hbn + ((size_t)(b*NN + n0 + r))*256 + m;
        #pragma unroll
        for (int c = 0; c < 16; c++)
            dst[c*16] = fmaxf(hacc[r][c]*a_s[c] + c_s[c], 0.f);
    }
}

// ================= padded-bucket adjacency ================================
__global__ void kZero() {
    int i = blockIdx.x*blockDim.x + threadIdx.x;
    if (i < NSUM) g_cnt[i] = 0;
}
__global__ void kFill(const int* __restrict__ ei) {
    int i = blockIdx.x*blockDim.x + threadIdx.x;
    if (i < NE) {
        int src = ei[i], dst = ei[NE + i];
        int p = atomicAdd(&g_cnt[dst], 1);
        if (p < CAP) g_adj[dst*CAP + p] = src;
    }
}

// ================= Kernel C: GIN layer 1 ===================================
// 1 warp per node, 8 nodes per 256-thread block. Thread tile: 8d x 4m (FFMA2).
__global__ __launch_bounds__(256) void kGin1(
    const float* __restrict__ eps1p,
    const float* __restrict__ W1a, const float* __restrict__ b1a,
    const float* __restrict__ W1b, const float* __restrict__ b1b)
{
    extern __shared__ u64 sd1[];
    u64* Wa = sd1;            // 16*64 = 1024
    u64* Wb = Wa + 1024;      // 4096
    u64* ba = Wb + 4096;      // 64
    u64* bb = ba + 64;        // 64
    u64* buf = bb + 64;       // 8*656

    const int tid = threadIdx.x;
    for (int i = tid; i < 1024; i += 256) {
        float w = W1a[i];
        Wa[wIdx(i >> 6, i & 63)] = pack2(w, w);
    }
    for (int i = tid; i < 4096; i += 256) {
        float w = W1b[i];
        Wb[wIdx(prow(i >> 6), i & 63)] = pack2(w, w);
    }
    if (tid < 64) { ba[tid] = pack2(b1a[tid], b1a[tid]); bb[tid] = pack2(b1b[tid], b1b[tid]); }
    __syncthreads();

    const int t = tid & 31, g = tid >> 5;
    const int v = blockIdx.x*8 + g;
    u64* Zb = buf + g*656;
    const float eps = 1.0f + eps1p[0];
    const u64 ep = pack2(eps, eps);

    // aggregation: node row = 128 u64; thread t covers u64 t*4 .. t*4+3
    u64 acc[4] = {0ull, 0ull, 0ull, 0ull};
    const int cnt = min(g_cnt[v], CAP);
    const int* adj = g_adj + v*CAP;
    for (int e = 0; e < cnt; e++) {
        const u64* src = (const u64*)(g_hbn + (size_t)adj[e]*256) + t*4;
        ulonglong2 x = *(const ulonglong2*)(src);
        ulonglong2 y = *(const ulonglong2*)(src + 2);
        acc[0] = fadd2(acc[0], x.x); acc[1] = fadd2(acc[1], x.y);
        acc[2] = fadd2(acc[2], y.x); acc[3] = fadd2(acc[3], y.y);
    }
    {
        const u64* hv = (const u64*)(g_hbn + (size_t)v*256) + t*4;
        ulonglong2 hx = *(const ulonglong2*)(hv);
        ulonglong2 hy = *(const ulonglong2*)(hv + 2);
        const int c = t >> 1, mp0 = (t & 1)*4;    // pair-linear p = t*4+i
        *(ulonglong2*)(Zb + c*10 + mp0)     = make_ulonglong2(ffma2(ep,hx.x,acc[0]), ffma2(ep,hx.y,acc[1]));
        *(ulonglong2*)(Zb + c*10 + mp0 + 2) = make_ulonglong2(ffma2(ep,hy.x,acc[2]), ffma2(ep,hy.y,acc[3]));
    }
    __syncwarp();

    const int dq = t & 7, mg = t >> 3;
    u64 C[8][2];

    // ---- GEMM1: z[16m,16c] @ W1a[16c,64d], relu ----
    #pragma unroll
    for (int r = 0; r < 8; r++) { u64 bv = ba[dq*8+r]; C[r][0]=bv; C[r][1]=bv; }
    #pragma unroll
    for (int c = 0; c < 16; c++) {
        ulonglong2 zp = *(const ulonglong2*)(Zb + c*10 + mg*2);
        const u64* wr = Wa + c*64 + dq*2;
        #pragma unroll
        for (int j = 0; j < 4; j++) {
            ulonglong2 w = *(const ulonglong2*)(wr + j*16);
            C[2*j  ][0] = ffma2(w.x, zp.x, C[2*j  ][0]);
            C[2*j  ][1] = ffma2(w.x, zp.y, C[2*j  ][1]);
            C[2*j+1][0] = ffma2(w.y, zp.x, C[2*j+1][0]);
            C[2*j+1][1] = ffma2(w.y, zp.y, C[2*j+1][1]);
        }
    }
    #pragma unroll
    for (int r = 0; r < 8; r++)
        #pragma unroll
        for (int e = 0; e < 2; e++) {
            float2 f = unpk(C[r][e]);
            C[r][e] = pack2(fmaxf(f.x,0.f), fmaxf(f.y,0.f));
        }
    __syncwarp();
    // store t permuted: actual d = dq*8+r -> buffer row r*8+dq (matches Wb preload)
    #pragma unroll
    for (int r = 0; r < 8; r++)
        *(ulonglong2*)(Zb + (r*8 + dq)*10 + mg*2) = make_ulonglong2(C[r][0], C[r][1]);
    __syncwarp();

    // ---- GEMM2: t[16m,64] @ W1b[64,64d], relu -> h1 ----
    #pragma unroll
    for (int r = 0; r < 8; r++) { u64 bv = bb[dq*8+r]; C[r][0]=bv; C[r][1]=bv; }
    #pragma unroll 4
    for (int c = 0; c < 64; c++) {
        ulonglong2 zp = *(const ulonglong2*)(Zb + c*10 + mg*2);
        const u64* wr = Wb + c*64 + dq*2;
        #pragma unroll
        for (int j = 0; j < 4; j++) {
            ulonglong2 w = *(const ulonglong2*)(wr + j*16);
            C[2*j  ][0] = ffma2(w.x, zp.x, C[2*j  ][0]);
            C[2*j  ][1] = ffma2(w.x, zp.y, C[2*j  ][1]);
            C[2*j+1][0] = ffma2(w.y, zp.x, C[2*j+1][0]);
            C[2*j+1][1] = ffma2(w.y, zp.y, C[2*j+1][1]);
        }
    }
    #pragma unroll
    for (int r = 0; r < 8; r++)
        #pragma unroll
        for (int e = 0; e < 2; e++) {
            float2 f = unpk(C[r][e]);
            C[r][e] = pack2(fmaxf(f.x,0.f), fmaxf(f.y,0.f));
        }
    __syncwarp();
    // stage (permuted rows again), then un-permute on the coalesced copy-out
    #pragma unroll
    for (int r = 0; r < 8; r++)
        *(ulonglong2*)(Zb + (r*8 + dq)*10 + mg*2) = make_ulonglong2(C[r][0], C[r][1]);
    __syncwarp();
    {
        u64* o = (u64*)(g_h1 + (size_t)v*1024);
        #pragma unroll
        for (int dd = 0; dd < 2; dd++) {
            int d = 2*t + dd;
            const u64* sp = Zb + prow(d)*10;
            ulonglong2* op = (ulonglong2*)(o + d*8);
            op[0] = *(const ulonglong2*)(sp + 0);
            op[1] = *(const ulonglong2*)(sp + 2);
            op[2] = *(const ulonglong2*)(sp + 4);
            op[3] = *(const ulonglong2*)(sp + 6);
        }
    }
}

// ================= Kernel D: GIN layer 2 + sample-sum ======================
__global__ __launch_bounds__(256) void kGin2(
    const float* __restrict__ eps2p,
    const float* __restrict__ W2a, const float* __restrict__ b2a,
    const float* __restrict__ W2b, const float* __restrict__ b2b,
    float* __restrict__ out)
{
    extern __shared__ u64 sd2[];
    u64* Wa = sd2;            // 4096
    u64* Wb = Wa + 4096;      // 4096
    u64* ba = Wb + 4096;      // 64
    u64* bb = ba + 64;        // 64
    u64* buf = bb + 64;       // 8*656

    const int tid = threadIdx.x;
    for (int i = tid; i < 4096; i += 256) {
        int c = i >> 6, d = i & 63;
        float wa = W2a[i], wb = W2b[i];
        Wa[wIdx(c, d)]       = pack2(wa, wa);
        Wb[wIdx(prow(c), d)] = pack2(wb, wb);
    }
    if (tid < 64) { ba[tid] = pack2(b2a[tid], b2a[tid]); bb[tid] = pack2(b2b[tid], b2b[tid]); }
    __syncthreads();

    const int t = tid & 31, g = tid >> 5;
    const int v = blockIdx.x*8 + g;
    u64* Zb = buf + g*656;
    const float eps = 1.0f + eps2p[0];
    const u64 ep = pack2(eps, eps);

    // aggregation: node row = 512 u64; thread t covers u64 t*16 .. t*16+15
    u64 acc[16];
    #pragma unroll
    for (int i = 0; i < 16; i++) acc[i] = 0ull;
    const int cnt = min(g_cnt[v], CAP);
    const int* adj = g_adj + v*CAP;
    for (int e = 0; e < cnt; e++) {
        const u64* src = (const u64*)(g_h1 + (size_t)adj[e]*1024) + t*16;
        #pragma unroll
        for (int i = 0; i < 16; i += 2) {
            ulonglong2 x = *(const ulonglong2*)(src + i);
            acc[i] = fadd2(acc[i], x.x); acc[i+1] = fadd2(acc[i+1], x.y);
        }
    }
    {
        const u64* hv = (const u64*)(g_h1 + (size_t)v*1024) + t*16;
        #pragma unroll
        for (int i = 0; i < 16; i += 2) {
            ulonglong2 h = *(const ulonglong2*)(hv + i);
            u64 z0 = ffma2(ep, h.x, acc[i]);
            u64 z1 = ffma2(ep, h.y, acc[i+1]);
            int c = 2*t + (i >> 3), mp = i & 7;   // rows c = 2t, 2t+1
            *(ulonglong2*)(Zb + c*10 + mp) = make_ulonglong2(z0, z1);
        }
    }
    __syncwarp();

    const int dq = t & 7, mg = t >> 3;
    u64 C[8][2];

    // ---- GEMM1: z @ W2a, relu ----
    #pragma unroll
    for (int r = 0; r < 8; r++) { u64 bv = ba[dq*8+r]; C[r][0]=bv; C[r][1]=bv; }
    #pragma unroll 4
    for (int c = 0; c < 64; c++) {
        ulonglong2 zp = *(const ulonglong2*)(Zb + c*10 + mg*2);
        const u64* wr = Wa + c*64 + dq*2;
        #pragma unroll
        for (int j = 0; j < 4; j++) {
            ulonglong2 w = *(const ulonglong2*)(wr + j*16);
            C[2*j  ][0] = ffma2(w.x, zp.x, C[2*j  ][0]);
            C[2*j  ][1] = ffma2(w.x, zp.y, C[2*j  ][1]);
            C[2*j+1][0] = ffma2(w.y, zp.x, C[2*j+1][0]);
            C[2*j+1][1] = ffma2(w.y, zp.y, C[2*j+1][1]);
        }
    }
    #pragma unroll
    for (int r = 0; r < 8; r++)
        #pragma unroll
        for (int e = 0; e < 2; e++) {
            float2 f = unpk(C[r][e]);
            C[r][e] = pack2(fmaxf(f.x,0.f), fmaxf(f.y,0.f));
        }
    __syncwarp();
    #pragma unroll
    for (int r = 0; r < 8; r++)
        *(ulonglong2*)(Zb + (r*8 + dq)*10 + mg*2) = make_ulonglong2(C[r][0], C[r][1]);
    __syncwarp();

    // ---- GEMM2: t @ W2b, relu, sum over m ----
    #pragma unroll
    for (int r = 0; r < 8; r++) { u64 bv = bb[dq*8+r]; C[r][0]=bv; C[r][1]=bv; }
    #pragma unroll 4
    for (int c = 0; c < 64; c++) {
        ulonglong2 zp = *(const ulonglong2*)(Zb + c*10 + mg*2);
        const u64* wr = Wb + c*64 + dq*2;
        #pragma unroll
        for (int j = 0; j < 4; j++) {
            ulonglong2 w = *(const ulonglong2*)(wr + j*16);
            C[2*j  ][0] = ffma2(w.x, zp.x, C[2*j  ][0]);
            C[2*j  ][1] = ffma2(w.x, zp.y, C[2*j  ][1]);
            C[2*j+1][0] = ffma2(w.y, zp.x, C[2*j+1][0]);
            C[2*j+1][1] = ffma2(w.y, zp.y, C[2*j+1][1]);
        }
    }
    float P[8];
    #pragma unroll
    for (int r = 0; r < 8; r++) {
        float2 a = unpk(C[r][0]), b = unpk(C[r][1]);
        P[r] = fmaxf(a.x,0.f)+fmaxf(a.y,0.f)+fmaxf(b.x,0.f)+fmaxf(b.y,0.f);
    }
    #pragma unroll
    for (int r = 0; r < 8; r++) {
        P[r] += __shfl_down_sync(0xffffffffu, P[r], 8);
        P[r] += __shfl_down_sync(0xffffffffu, P[r], 16);
    }
    if (t < 8) {
        float* op = out + (size_t)v*64 + t*8;
        *(float4*)(op)     = make_float4(P[0], P[1], P[2], P[3]);
        *(float4*)(op + 4) = make_float4(P[4], P[5], P[6], P[7]);
    }
}

// ================= launch ==================================================
extern "C" void kernel_launch(void* const* d_in, const int* in_sizes, int n_in,
                              void* d_out, int out_size)
{
    const float* lap  = (const float*)d_in[0];
    const float* W0   = (const float*)d_in[1];
    const float* mlpW = (const float*)d_in[2];
    const float* mlpb = (const float*)d_in[3];
    const float* bng  = (const float*)d_in[4];
    const float* bnb  = (const float*)d_in[5];
    const float* eps1 = (const float*)d_in[6];
    const float* W1a  = (const float*)d_in[7];
    const float* b1a  = (const float*)d_in[8];
    const float* W1b  = (const float*)d_in[9];
    const float* b1b  = (const float*)d_in[10];
    const float* eps2 = (const float*)d_in[11];
    const float* W2a  = (const float*)d_in[12];
    const float* b2a  = (const float*)d_in[13];
    const float* W2b  = (const float*)d_in[14];
    const float* b2b  = (const float*)d_in[15];
    const int*   ei   = (const int*)d_in[16];
    float* out = (float*)d_out;

    const int SMEM_A  = 21696 * 4;                         // 86784 B
    const int SMEM_G1 = (1024+4096+128 + 8*656) * 8;       // 83968 B
    const int SMEM_G2 = (4096+4096+128 + 8*656) * 8;       // 108544 B
    cudaFuncSetAttribute(kA,    cudaFuncAttributeMaxDynamicSharedMemorySize, SMEM_A);
    cudaFuncSetAttribute(kGin1, cudaFuncAttributeMaxDynamicSharedMemorySize, SMEM_G1);
    cudaFuncSetAttribute(kGin2, cudaFuncAttributeMaxDynamicSharedMemorySize, SMEM_G2);

    kZero<<<NSUM/256, 256>>>();
    kFill<<<NE/256, 256>>>(ei);
    kA   <<<BG, 512, SMEM_A>>>(lap, W0, mlpW, mlpb, bng, bnb);
    kGin1<<<NSUM/8, 256, SMEM_G1>>>(eps1, W1a, b1a, W1b, b1b);
    kGin2<<<NSUM/8, 256, SMEM_G2>>>(eps2, W2a, b2a, W2b, b2b, out);
}

// round 8
// speedup vs baseline: 1.5265x; 1.1265x over previous
#include <cuda_runtime.h>

#define BG 128
#define NN 128
#define NE 262144
#define NSUM (BG*NN)   // 16384
#define CAP 96

typedef unsigned long long u64;

// ---------------- scratch (static device globals; no runtime alloc) --------
__device__ float g_hbn[NSUM*256];    // per node [c][m], m fast   16 MB
__device__ float g_h1 [NSUM*1024];   // per node [d][m], m fast   64 MB
__device__ int   g_cnt [NSUM];
__device__ int   g_adj [NSUM*CAP];

// ---------------- f32x2 helpers -------------------------------------------
__device__ __forceinline__ u64 ffma2(u64 a, u64 b, u64 c) {
    u64 d; asm("fma.rn.f32x2 %0,%1,%2,%3;" : "=l"(d) : "l"(a), "l"(b), "l"(c));
    return d;
}
__device__ __forceinline__ u64 fadd2(u64 a, u64 b) {
    u64 d; asm("add.rn.f32x2 %0,%1,%2;" : "=l"(d) : "l"(a), "l"(b));
    return d;
}
__device__ __forceinline__ u64 pack2(float x, float y) {
    u64 r; asm("mov.b64 %0,{%1,%2};" : "=l"(r) : "f"(x), "f"(y));
    return r;
}
__device__ __forceinline__ float2 unpk(u64 v) {
    float2 r; asm("mov.b64 {%0,%1},%2;" : "=f"(r.x), "=f"(r.y) : "l"(v));
    return r;
}
// weight smem slot for (reduction row c, output d)
__device__ __forceinline__ int wIdx(int c, int d) {
    int dq = d >> 3, rr = d & 7;
    return c*64 + (rr >> 1)*16 + dq*2 + (rr & 1);
}
// permuted buffer row (involution) for GEMM1->GEMM2 staging
__device__ __forceinline__ int prow(int c) { return ((c & 7) << 3) | (c >> 3); }

// ================= Kernel A: poly filter + MLP + BatchNorm + ReLU =========
__global__ __launch_bounds__(512) void kA(
    const float* __restrict__ lap, const float* __restrict__ W0,
    const float* __restrict__ mlpW, const float* __restrict__ mlpb,
    const float* __restrict__ bng,  const float* __restrict__ bnb)
{
    extern __shared__ float sm[];
    float* lap_s = sm;                    // 128*132
    float* w_s   = lap_s + 128*132;       // 2*2064
    float* mw_s  = w_s + 2*2064;          // 128
    float* redS  = mw_s + 128;            // 256
    float* redQ  = redS + 256;            // 256
    float* a_s   = redQ + 256;            // 16
    float* c_s   = a_s + 16;              // 16

    const int b = blockIdx.x, tid = threadIdx.x;
    const float* lb = lap + (size_t)b*NN*NN;
    for (int q = tid; q < NN*NN/4; q += 512) {
        int n = q >> 5, j4 = (q & 31) << 2;
        *(float4*)(lap_s + n*132 + j4) = *(const float4*)(lb + n*NN + j4);
    }
    if (tid < 128) mw_s[tid] = mlpW[tid];

    const int m = tid & 15, g = tid >> 4, n0 = g << 2;

    float hacc[4][16];
    #pragma unroll
    for (int r = 0; r < 4; r++)
        #pragma unroll
        for (int c = 0; c < 16; c++) hacc[r][c] = 0.f;

    float wv[4];
    #pragma unroll
    for (int r = 0; r < 4; r++) {
        wv[r] = W0[(size_t)b*NN*16 + (n0+r)*16 + m];
        w_s[m*129 + n0 + r] = wv[r];
    }
    __syncthreads();
    #pragma unroll
    for (int r = 0; r < 4; r++)
        #pragma unroll
        for (int c = 0; c < 16; c++) hacc[r][c] += wv[r]*mw_s[c];

    int cur = 0;
    for (int k = 1; k < 8; k++) {
        float acc0=0.f, acc1=0.f, acc2=0.f, acc3=0.f;
        const float* wr = w_s + cur*2064 + m*129;
        const float* l0 = lap_s + (n0+0)*132;
        const float* l1 = lap_s + (n0+1)*132;
        const float* l2 = lap_s + (n0+2)*132;
        const float* l3 = lap_s + (n0+3)*132;
        #pragma unroll 8
        for (int j = 0; j < NN; j += 4) {
            float w0=wr[j], w1=wr[j+1], w2=wr[j+2], w3=wr[j+3];
            float4 a  = *(const float4*)(l0+j);
            float4 b4 = *(const float4*)(l1+j);
            float4 c4 = *(const float4*)(l2+j);
            float4 d4 = *(const float4*)(l3+j);
            acc0 += a.x *w0 + a.y *w1 + a.z *w2 + a.w *w3;
            acc1 += b4.x*w0 + b4.y*w1 + b4.z*w2 + b4.w*w3;
            acc2 += c4.x*w0 + c4.y*w1 + c4.z*w2 + c4.w*w3;
            acc3 += d4.x*w0 + d4.y*w1 + d4.z*w2 + d4.w*w3;
        }
        float* wn = w_s + (cur^1)*2064 + m*129;
        wn[n0]=acc0; wn[n0+1]=acc1; wn[n0+2]=acc2; wn[n0+3]=acc3;
        const float* mw = mw_s + k*16;
        float av[4] = {acc0, acc1, acc2, acc3};
        #pragma unroll
        for (int r = 0; r < 4; r++)
            #pragma unroll
            for (int c = 0; c < 16; c++) hacc[r][c] += av[r]*mw[c];
        __syncthreads();
        cur ^= 1;
    }
    #pragma unroll
    for (int c = 0; c < 16; c++) {
        float bb = mlpb[c];
        #pragma unroll
        for (int r = 0; r < 4; r++) hacc[r][c] += bb;
    }
    float s[16], q[16];
    #pragma unroll
    for (int c = 0; c < 16; c++) {
        s[c] = hacc[0][c]+hacc[1][c]+hacc[2][c]+hacc[3][c];
        q[c] = hacc[0][c]*hacc[0][c]+hacc[1][c]*hacc[1][c]
             + hacc[2][c]*hacc[2][c]+hacc[3][c]*hacc[3][c];
    }
    #pragma unroll
    for (int o = 16; o > 0; o >>= 1) {
        #pragma unroll
        for (int c = 0; c < 16; c++) {
            s[c] += __shfl_xor_sync(0xffffffffu, s[c], o);
            q[c] += __shfl_xor_sync(0xffffffffu, q[c], o);
        }
    }
    const int warp = tid >> 5, lane = tid & 31;
    if (lane == 0) {
        #pragma unroll
        for (int c = 0; c < 16; c++) { redS[warp*16+c]=s[c]; redQ[warp*16+c]=q[c]; }
    }
    __syncthreads();
    if (tid < 16) {
        float S=0.f, Q=0.f;
        #pragma unroll
        for (int w = 0; w < 16; w++) { S += redS[w*16+tid]; Q += redQ[w*16+tid]; }
        float mean = S * (1.0f/2048.0f);
        float var  = Q * (1.0f/2048.0f) - mean*mean;
        float rstd = rsqrtf(var + 1e-5f);
        float gch  = bng[tid];
        a_s[tid] = rstd * gch;
        c_s[tid] = bnb[tid] - mean * rstd * gch;
    }
    __syncthreads();
    #pragma unroll
    for (int r = 0; r < 4; r++) {
        float* dst = g_hbn + ((size_t)(b*NN + n0 + r))*256 + m;
        #pragma unroll
        for (int c = 0; c < 16; c++)
            dst[c*16] = fmaxf(hacc[r][c]*a_s[c] + c_s[c], 0.f);
    }
}

// ================= padded-bucket adjacency ================================
__global__ void kZero() {
    int i = blockIdx.x*blockDim.x + threadIdx.x;
    if (i < NSUM) g_cnt[i] = 0;
}
__global__ void kFill(const int* __restrict__ ei) {
    int i = blockIdx.x*blockDim.x + threadIdx.x;
    if (i < NE) {
        int src = ei[i], dst = ei[NE + i];
        int p = atomicAdd(&g_cnt[dst], 1);
        if (p < CAP) g_adj[dst*CAP + p] = src;
    }
}

// ================= Kernel C: GIN layer 1 ===================================
// 1 warp/node, 8 nodes/block. Tile 8d x 4m per thread. W smem buffer reused
// (Wa then Wb, block-wide sync between). launch_bounds(256,2) -> 128 regs.
__global__ __launch_bounds__(256, 2) void kGin1(
    const float* __restrict__ eps1p,
    const float* __restrict__ W1a, const float* __restrict__ b1a,
    const float* __restrict__ W1b, const float* __restrict__ b1b)
{
    extern __shared__ u64 sd1[];
    u64* W  = sd1;            // 4096 (Wa first, then Wb)
    u64* ba = W + 4096;       // 64
    u64* bb = ba + 64;        // 64
    u64* buf = bb + 64;       // 8*656

    const int tid = threadIdx.x;
    for (int i = tid; i < 1024; i += 256) {
        float w = W1a[i];
        W[wIdx(i >> 6, i & 63)] = pack2(w, w);
    }
    if (tid < 64) { ba[tid] = pack2(b1a[tid], b1a[tid]); bb[tid] = pack2(b1b[tid], b1b[tid]); }
    __syncthreads();

    const int t = tid & 31, g = tid >> 5;
    const int v = blockIdx.x*8 + g;
    u64* Zb = buf + g*656;
    const float eps = 1.0f + eps1p[0];
    const u64 ep = pack2(eps, eps);

    // aggregation: node row = 128 u64; thread t covers u64 t*4 .. t*4+3
    u64 acc[4] = {0ull, 0ull, 0ull, 0ull};
    const int cnt = min(g_cnt[v], CAP);
    const int* adj = g_adj + v*CAP;
    #pragma unroll 2
    for (int e = 0; e < cnt; e++) {
        const u64* src = (const u64*)(g_hbn + (size_t)adj[e]*256) + t*4;
        ulonglong2 x = *(const ulonglong2*)(src);
        ulonglong2 y = *(const ulonglong2*)(src + 2);
        acc[0] = fadd2(acc[0], x.x); acc[1] = fadd2(acc[1], x.y);
        acc[2] = fadd2(acc[2], y.x); acc[3] = fadd2(acc[3], y.y);
    }
    {
        const u64* hv = (const u64*)(g_hbn + (size_t)v*256) + t*4;
        ulonglong2 hx = *(const ulonglong2*)(hv);
        ulonglong2 hy = *(const ulonglong2*)(hv + 2);
        const int c = t >> 1, mp0 = (t & 1)*4;
        *(ulonglong2*)(Zb + c*10 + mp0)     = make_ulonglong2(ffma2(ep,hx.x,acc[0]), ffma2(ep,hx.y,acc[1]));
        *(ulonglong2*)(Zb + c*10 + mp0 + 2) = make_ulonglong2(ffma2(ep,hy.x,acc[2]), ffma2(ep,hy.y,acc[3]));
    }
    __syncwarp();

    const int dq = t & 7, mg = t >> 3;
    u64 C[8][2];

    // ---- GEMM1: z[16m,16c] @ W1a[16c,64d], relu ----
    #pragma unroll
    for (int r = 0; r < 8; r++) { u64 bv = ba[dq*8+r]; C[r][0]=bv; C[r][1]=bv; }
    #pragma unroll
    for (int c = 0; c < 16; c++) {
        ulonglong2 zp = *(const ulonglong2*)(Zb + c*10 + mg*2);
        const u64* wr = W + c*64 + dq*2;
        #pragma unroll
        for (int j = 0; j < 4; j++) {
            ulonglong2 w = *(const ulonglong2*)(wr + j*16);
            C[2*j  ][0] = ffma2(w.x, zp.x, C[2*j  ][0]);
            C[2*j  ][1] = ffma2(w.x, zp.y, C[2*j  ][1]);
            C[2*j+1][0] = ffma2(w.y, zp.x, C[2*j+1][0]);
            C[2*j+1][1] = ffma2(w.y, zp.y, C[2*j+1][1]);
        }
    }
    #pragma unroll
    for (int r = 0; r < 8; r++)
        #pragma unroll
        for (int e = 0; e < 2; e++) {
            float2 f = unpk(C[r][e]);
            C[r][e] = pack2(fmaxf(f.x,0.f), fmaxf(f.y,0.f));
        }
    // all warps done reading Wa before overwrite with Wb
    __syncthreads();
    #pragma unroll
    for (int r = 0; r < 8; r++)
        *(ulonglong2*)(Zb + (r*8 + dq)*10 + mg*2) = make_ulonglong2(C[r][0], C[r][1]);
    for (int i = tid; i < 4096; i += 256) {
        float w = W1b[i];
        W[wIdx(prow(i >> 6), i & 63)] = pack2(w, w);
    }
    __syncthreads();

    // ---- GEMM2: t[16m,64] @ W1b[64,64d], relu -> h1 ----
    #pragma unroll
    for (int r = 0; r < 8; r++) { u64 bv = bb[dq*8+r]; C[r][0]=bv; C[r][1]=bv; }
    #pragma unroll 4
    for (int c = 0; c < 64; c++) {
        ulonglong2 zp = *(const ulonglong2*)(Zb + c*10 + mg*2);
        const u64* wr = W + c*64 + dq*2;
        #pragma unroll
        for (int j = 0; j < 4; j++) {
            ulonglong2 w = *(const ulonglong2*)(wr + j*16);
            C[2*j  ][0] = ffma2(w.x, zp.x, C[2*j  ][0]);
            C[2*j  ][1] = ffma2(w.x, zp.y, C[2*j  ][1]);
            C[2*j+1][0] = ffma2(w.y, zp.x, C[2*j+1][0]);
            C[2*j+1][1] = ffma2(w.y, zp.y, C[2*j+1][1]);
        }
    }
    #pragma unroll
    for (int r = 0; r < 8; r++)
        #pragma unroll
        for (int e = 0; e < 2; e++) {
            float2 f = unpk(C[r][e]);
            C[r][e] = pack2(fmaxf(f.x,0.f), fmaxf(f.y,0.f));
        }
    __syncwarp();
    #pragma unroll
    for (int r = 0; r < 8; r++)
        *(ulonglong2*)(Zb + (r*8 + dq)*10 + mg*2) = make_ulonglong2(C[r][0], C[r][1]);
    __syncwarp();
    {
        u64* o = (u64*)(g_h1 + (size_t)v*1024);
        #pragma unroll
        for (int dd = 0; dd < 2; dd++) {
            int d = 2*t + dd;
            const u64* sp = Zb + prow(d)*10;
            ulonglong2* op = (ulonglong2*)(o + d*8);
            op[0] = *(const ulonglong2*)(sp + 0);
            op[1] = *(const ulonglong2*)(sp + 2);
            op[2] = *(const ulonglong2*)(sp + 4);
            op[3] = *(const ulonglong2*)(sp + 6);
        }
    }
}

// ================= Kernel D: GIN layer 2 + sample-sum ======================
__global__ __launch_bounds__(256, 2) void kGin2(
    const float* __restrict__ eps2p,
    const float* __restrict__ W2a, const float* __restrict__ b2a,
    const float* __restrict__ W2b, const float* __restrict__ b2b,
    float* __restrict__ out)
{
    extern __shared__ u64 sd2[];
    u64* W  = sd2;            // 4096 (Wa first, then Wb)
    u64* ba = W + 4096;       // 64
    u64* bb = ba + 64;        // 64
    u64* buf = bb + 64;       // 8*656

    const int tid = threadIdx.x;
    for (int i = tid; i < 4096; i += 256) {
        float wa = W2a[i];
        W[wIdx(i >> 6, i & 63)] = pack2(wa, wa);
    }
    if (tid < 64) { ba[tid] = pack2(b2a[tid], b2a[tid]); bb[tid] = pack2(b2b[tid], b2b[tid]); }
    __syncthreads();

    const int t = tid & 31, g = tid >> 5;
    const int v = blockIdx.x*8 + g;
    u64* Zb = buf + g*656;
    const float eps = 1.0f + eps2p[0];
    const u64 ep = pack2(eps, eps);

    // aggregation: node row = 512 u64; thread t covers u64 t*16 .. t*16+15
    u64 acc[16];
    #pragma unroll
    for (int i = 0; i < 16; i++) acc[i] = 0ull;
    const int cnt = min(g_cnt[v], CAP);
    const int* adj = g_adj + v*CAP;
    #pragma unroll 2
    for (int e = 0; e < cnt; e++) {
        const u64* src = (const u64*)(g_h1 + (size_t)adj[e]*1024) + t*16;
        #pragma unroll
        for (int i = 0; i < 16; i += 2) {
            ulonglong2 x = *(const ulonglong2*)(src + i);
            acc[i] = fadd2(acc[i], x.x); acc[i+1] = fadd2(acc[i+1], x.y);
        }
    }
    {
        const u64* hv = (const u64*)(g_h1 + (size_t)v*1024) + t*16;
        #pragma unroll
        for (int i = 0; i < 16; i += 2) {
            ulonglong2 h = *(const ulonglong2*)(hv + i);
            u64 z0 = ffma2(ep, h.x, acc[i]);
            u64 z1 = ffma2(ep, h.y, acc[i+1]);
            int c = 2*t + (i >> 3), mp = i & 7;
            *(ulonglong2*)(Zb + c*10 + mp) = make_ulonglong2(z0, z1);
        }
    }
    __syncwarp();

    const int dq = t & 7, mg = t >> 3;
    u64 C[8][2];

    // ---- GEMM1: z @ W2a, relu ----
    #pragma unroll
    for (int r = 0; r < 8; r++) { u64 bv = ba[dq*8+r]; C[r][0]=bv; C[r][1]=bv; }
    #pragma unroll 4
    for (int c = 0; c < 64; c++) {
        ulonglong2 zp = *(const ulonglong2*)(Zb + c*10 + mg*2);
        const u64* wr = W + c*64 + dq*2;
        #pragma unroll
        for (int j = 0; j < 4; j++) {
            ulonglong2 w = *(const ulonglong2*)(wr + j*16);
            C[2*j  ][0] = ffma2(w.x, zp.x, C[2*j  ][0]);
            C[2*j  ][1] = ffma2(w.x, zp.y, C[2*j  ][1]);
            C[2*j+1][0] = ffma2(w.y, zp.x, C[2*j+1][0]);
            C[2*j+1][1] = ffma2(w.y, zp.y, C[2*j+1][1]);
        }
    }
    #pragma unroll
    for (int r = 0; r < 8; r++)
        #pragma unroll
        for (int e = 0; e < 2; e++) {
            float2 f = unpk(C[r][e]);
            C[r][e] = pack2(fmaxf(f.x,0.f), fmaxf(f.y,0.f));
        }
    // all warps done reading Wa before overwrite with Wb
    __syncthreads();
    #pragma unroll
    for (int r = 0; r < 8; r++)
        *(ulonglong2*)(Zb + (r*8 + dq)*10 + mg*2) = make_ulonglong2(C[r][0], C[r][1]);
    for (int i = tid; i < 4096; i += 256) {
        float wb = W2b[i];
        W[wIdx(prow(i >> 6), i & 63)] = pack2(wb, wb);
    }
    __syncthreads();

    // ---- GEMM2: t @ W2b, relu, sum over m ----
    #pragma unroll
    for (int r = 0; r < 8; r++) { u64 bv = bb[dq*8+r]; C[r][0]=bv; C[r][1]=bv; }
    #pragma unroll 4
    for (int c = 0; c < 64; c++) {
        ulonglong2 zp = *(const ulonglong2*)(Zb + c*10 + mg*2);
        const u64* wr = W + c*64 + dq*2;
        #pragma unroll
        for (int j = 0; j < 4; j++) {
            ulonglong2 w = *(const ulonglong2*)(wr + j*16);
            C[2*j  ][0] = ffma2(w.x, zp.x, C[2*j  ][0]);
            C[2*j  ][1] = ffma2(w.x, zp.y, C[2*j  ][1]);
            C[2*j+1][0] = ffma2(w.y, zp.x, C[2*j+1][0]);
            C[2*j+1][1] = ffma2(w.y, zp.y, C[2*j+1][1]);
        }
    }
    float P[8];
    #pragma unroll
    for (int r = 0; r < 8; r++) {
        float2 a = unpk(C[r][0]), b = unpk(C[r][1]);
        P[r] = fmaxf(a.x,0.f)+fmaxf(a.y,0.f)+fmaxf(b.x,0.f)+fmaxf(b.y,0.f);
    }
    #pragma unroll
    for (int r = 0; r < 8; r++) {
        P[r] += __shfl_down_sync(0xffffffffu, P[r], 8);
        P[r] += __shfl_down_sync(0xffffffffu, P[r], 16);
    }
    if (t < 8) {
        float* op = out + (size_t)v*64 + t*8;
        *(float4*)(op)     = make_float4(P[0], P[1], P[2], P[3]);
        *(float4*)(op + 4) = make_float4(P[4], P[5], P[6], P[7]);
    }
}

// ================= launch ==================================================
extern "C" void kernel_launch(void* const* d_in, const int* in_sizes, int n_in,
                              void* d_out, int out_size)
{
    const float* lap  = (const float*)d_in[0];
    const float* W0   = (const float*)d_in[1];
    const float* mlpW = (const float*)d_in[2];
    const float* mlpb = (const float*)d_in[3];
    const float* bng  = (const float*)d_in[4];
    const float* bnb  = (const float*)d_in[5];
    const float* eps1 = (const float*)d_in[6];
    const float* W1a  = (const float*)d_in[7];
    const float* b1a  = (const float*)d_in[8];
    const float* W1b  = (const float*)d_in[9];
    const float* b1b  = (const float*)d_in[10];
    const float* eps2 = (const float*)d_in[11];
    const float* W2a  = (const float*)d_in[12];
    const float* b2a  = (const float*)d_in[13];
    const float* W2b  = (const float*)d_in[14];
    const float* b2b  = (const float*)d_in[15];
    const int*   ei   = (const int*)d_in[16];
    float* out = (float*)d_out;

    const int SMEM_A = 21696 * 4;                    // 86784 B
    const int SMEM_G = (4096 + 128 + 8*656) * 8;     // 75776 B -> 2 blocks/SM
    cudaFuncSetAttribute(kA,    cudaFuncAttributeMaxDynamicSharedMemorySize, SMEM_A);
    cudaFuncSetAttribute(kGin1, cudaFuncAttributeMaxDynamicSharedMemorySize, SMEM_G);
    cudaFuncSetAttribute(kGin2, cudaFuncAttributeMaxDynamicSharedMemorySize, SMEM_G);

    kZero<<<NSUM/256, 256>>>();
    kFill<<<NE/256, 256>>>(ei);
    kA   <<<BG, 512, SMEM_A>>>(lap, W0, mlpW, mlpb, bng, bnb);
    kGin1<<<NSUM/8, 256, SMEM_G>>>(eps1, W1a, b1a, W1b, b1b);
    kGin2<<<NSUM/8, 256, SMEM_G>>>(eps2, W2a, b2a, W2b, b2b, out);
}

// round 10
// speedup vs baseline: 3.8705x; 2.5355x over previous
#include <cuda_runtime.h>

#define BG 128
#define NN 128
#define NE 262144
#define NSUM (BG*NN)   // 16384
#define CAP 96

typedef unsigned int u32;

// ---------------- scratch (static device globals; no runtime alloc) --------
__device__ float g_hbn[NSUM*256];    // per node [m][c], c fast   16 MB
__device__ float g_h1 [NSUM*1024];   // per node [m][d], d fast   64 MB
__device__ int   g_cnt [NSUM];
__device__ int   g_adj [NSUM*CAP];

// ---------------- tf32 mma helpers ----------------------------------------
__device__ __forceinline__ u32 f2tf(float f) {
    u32 r; asm("cvt.rna.tf32.f32 %0, %1;" : "=r"(r) : "f"(f)); return r;
}
__device__ __forceinline__ void mma8(float4& c, u32 a0, u32 a1, u32 a2, u32 a3,
                                     u32 b0, u32 b1) {
    asm("mma.sync.aligned.m16n8k8.row.col.f32.tf32.tf32.f32 "
        "{%0,%1,%2,%3},{%4,%5,%6,%7},{%8,%9},{%0,%1,%2,%3};"
        : "+f"(c.x), "+f"(c.y), "+f"(c.z), "+f"(c.w)
        : "r"(a0), "r"(a1), "r"(a2), "r"(a3), "r"(b0), "r"(b1));
}

// ================= Kernel A: poly filter + MLP + BatchNorm + ReLU =========
__global__ __launch_bounds__(512) void kA(
    const float* __restrict__ lap, const float* __restrict__ W0,
    const float* __restrict__ mlpW, const float* __restrict__ mlpb,
    const float* __restrict__ bng,  const float* __restrict__ bnb)
{
    extern __shared__ float sm[];
    float* lap_s = sm;                    // 128*132
    float* w_s   = lap_s + 128*132;       // 2*2064
    float* mw_s  = w_s + 2*2064;          // 128
    float* redS  = mw_s + 128;            // 256
    float* redQ  = redS + 256;            // 256
    float* a_s   = redQ + 256;            // 16
    float* c_s   = a_s + 16;              // 16

    const int b = blockIdx.x, tid = threadIdx.x;
    const float* lb = lap + (size_t)b*NN*NN;
    for (int q = tid; q < NN*NN/4; q += 512) {
        int n = q >> 5, j4 = (q & 31) << 2;
        *(float4*)(lap_s + n*132 + j4) = *(const float4*)(lb + n*NN + j4);
    }
    if (tid < 128) mw_s[tid] = mlpW[tid];

    const int m = tid & 15, g = tid >> 4, n0 = g << 2;

    float hacc[4][16];
    #pragma unroll
    for (int r = 0; r < 4; r++)
        #pragma unroll
        for (int c = 0; c < 16; c++) hacc[r][c] = 0.f;

    float wv[4];
    #pragma unroll
    for (int r = 0; r < 4; r++) {
        wv[r] = W0[(size_t)b*NN*16 + (n0+r)*16 + m];
        w_s[m*129 + n0 + r] = wv[r];
    }
    __syncthreads();
    #pragma unroll
    for (int r = 0; r < 4; r++)
        #pragma unroll
        for (int c = 0; c < 16; c++) hacc[r][c] += wv[r]*mw_s[c];

    int cur = 0;
    for (int k = 1; k < 8; k++) {
        float acc0=0.f, acc1=0.f, acc2=0.f, acc3=0.f;
        const float* wr = w_s + cur*2064 + m*129;
        const float* l0 = lap_s + (n0+0)*132;
        const float* l1 = lap_s + (n0+1)*132;
        const float* l2 = lap_s + (n0+2)*132;
        const float* l3 = lap_s + (n0+3)*132;
        #pragma unroll 8
        for (int j = 0; j < NN; j += 4) {
            float w0=wr[j], w1=wr[j+1], w2=wr[j+2], w3=wr[j+3];
            float4 a  = *(const float4*)(l0+j);
            float4 b4 = *(const float4*)(l1+j);
            float4 c4 = *(const float4*)(l2+j);
            float4 d4 = *(const float4*)(l3+j);
            acc0 += a.x *w0 + a.y *w1 + a.z *w2 + a.w *w3;
            acc1 += b4.x*w0 + b4.y*w1 + b4.z*w2 + b4.w*w3;
            acc2 += c4.x*w0 + c4.y*w1 + c4.z*w2 + c4.w*w3;
            acc3 += d4.x*w0 + d4.y*w1 + d4.z*w2 + d4.w*w3;
        }
        float* wn = w_s + (cur^1)*2064 + m*129;
        wn[n0]=acc0; wn[n0+1]=acc1; wn[n0+2]=acc2; wn[n0+3]=acc3;
        const float* mw = mw_s + k*16;
        float av[4] = {acc0, acc1, acc2, acc3};
        #pragma unroll
        for (int r = 0; r < 4; r++)
            #pragma unroll
            for (int c = 0; c < 16; c++) hacc[r][c] += av[r]*mw[c];
        __syncthreads();
        cur ^= 1;
    }
    #pragma unroll
    for (int c = 0; c < 16; c++) {
        float bb = mlpb[c];
        #pragma unroll
        for (int r = 0; r < 4; r++) hacc[r][c] += bb;
    }
    float s[16], q[16];
    #pragma unroll
    for (int c = 0; c < 16; c++) {
        s[c] = hacc[0][c]+hacc[1][c]+hacc[2][c]+hacc[3][c];
        q[c] = hacc[0][c]*hacc[0][c]+hacc[1][c]*hacc[1][c]
             + hacc[2][c]*hacc[2][c]+hacc[3][c]*hacc[3][c];
    }
    #pragma unroll
    for (int o = 16; o > 0; o >>= 1) {
        #pragma unroll
        for (int c = 0; c < 16; c++) {
            s[c] += __shfl_xor_sync(0xffffffffu, s[c], o);
            q[c] += __shfl_xor_sync(0xffffffffu, q[c], o);
        }
    }
    const int warp = tid >> 5, lane = tid & 31;
    if (lane == 0) {
        #pragma unroll
        for (int c = 0; c < 16; c++) { redS[warp*16+c]=s[c]; redQ[warp*16+c]=q[c]; }
    }
    __syncthreads();
    if (tid < 16) {
        float S=0.f, Q=0.f;
        #pragma unroll
        for (int w = 0; w < 16; w++) { S += redS[w*16+tid]; Q += redQ[w*16+tid]; }
        float mean = S * (1.0f/2048.0f);
        float var  = Q * (1.0f/2048.0f) - mean*mean;
        float rstd = rsqrtf(var + 1e-5f);
        float gch  = bng[tid];
        a_s[tid] = rstd * gch;
        c_s[tid] = bnb[tid] - mean * rstd * gch;
    }
    __syncthreads();
    // store [m][c] per node: thread owns 16 contiguous floats -> 4x float4
    #pragma unroll
    for (int r = 0; r < 4; r++) {
        float tmp[16];
        #pragma unroll
        for (int c = 0; c < 16; c++)
            tmp[c] = fmaxf(hacc[r][c]*a_s[c] + c_s[c], 0.f);
        float* dst = g_hbn + ((size_t)(b*NN + n0 + r))*256 + m*16;
        *(float4*)(dst+ 0) = make_float4(tmp[0], tmp[1], tmp[2], tmp[3]);
        *(float4*)(dst+ 4) = make_float4(tmp[4], tmp[5], tmp[6], tmp[7]);
        *(float4*)(dst+ 8) = make_float4(tmp[8], tmp[9], tmp[10],tmp[11]);
        *(float4*)(dst+12) = make_float4(tmp[12],tmp[13],tmp[14],tmp[15]);
    }
}

// ================= padded-bucket adjacency ================================
__global__ void kZero() {
    int i = blockIdx.x*blockDim.x + threadIdx.x;
    if (i < NSUM) g_cnt[i] = 0;
}
__global__ void kFill(const int* __restrict__ ei) {
    int i = blockIdx.x*blockDim.x + threadIdx.x;
    if (i < NE) {
        int src = ei[i], dst = ei[NE + i];
        int p = atomicAdd(&g_cnt[dst], 1);
        if (p < CAP) g_adj[dst*CAP + p] = src;
    }
}

// ================= Kernel C: GIN layer 1 (tensor-core tf32) ================
// 8 warps/block, 2 nodes/warp, 16 nodes/block.
// GEMM1: z[16,16] @ W1a[16,64]; GEMM2: t[16,64] @ W1b[64,64] -> h1 (fp32).
__global__ __launch_bounds__(256, 2) void kGin1(
    const float* __restrict__ eps1p,
    const float* __restrict__ W1a, const float* __restrict__ b1a,
    const float* __restrict__ W1b, const float* __restrict__ b1b)
{
    extern __shared__ u32 sh1[];
    u32*   Wa  = sh1;                 // 16*72 = 1152 u32
    u32*   Wb  = Wa + 1152;           // 64*72 = 4608 u32
    float* bia = (float*)(Wb + 4608); // 64
    float* bib = bia + 64;            // 64
    u32*   zS  = (u32*)(bib + 64);    // 16 nodes * 16*20 = 5120 u32
    u32*   tS  = zS + 5120;           // 16 nodes * 16*68 = 17408 u32

    const int tid = threadIdx.x;
    for (int i = tid; i < 1024; i += 256)
        Wa[(i >> 6)*72 + (i & 63)] = f2tf(W1a[i]);
    for (int i = tid; i < 4096; i += 256)
        Wb[(i >> 6)*72 + (i & 63)] = f2tf(W1b[i]);
    if (tid < 64) { bia[tid] = b1a[tid]; bib[tid] = b1b[tid]; }
    __syncthreads();

    const int lane = tid & 31, w = tid >> 5;
    const int q = lane & 3, r = lane >> 2;
    const int vb = blockIdx.x*16 + w*2;
    const float eps = 1.0f + eps1p[0];

    // ---- aggregation (fp32) -> z smem (tf32), stride 20 ----
    #pragma unroll
    for (int nd = 0; nd < 2; nd++) {
        const int v = vb + nd;
        u32* zb = zS + (w*2 + nd)*320;
        float4 A0 = make_float4(0.f,0.f,0.f,0.f), A1 = A0;
        const int cnt = min(g_cnt[v], CAP);
        const int* adj = g_adj + v*CAP;
        for (int e = 0; e < cnt; e++) {
            const float* src = g_hbn + (size_t)adj[e]*256 + lane*4;
            float4 x = *(const float4*)(src);
            float4 y = *(const float4*)(src + 128);
            A0.x+=x.x; A0.y+=x.y; A0.z+=x.z; A0.w+=x.w;
            A1.x+=y.x; A1.y+=y.y; A1.z+=y.z; A1.w+=y.w;
        }
        const float* own = g_hbn + (size_t)v*256 + lane*4;
        float4 o0 = *(const float4*)(own);
        float4 o1 = *(const float4*)(own + 128);
        // rows: j=0 -> m = lane>>2 ; j=1 -> m = 8 + lane>>2 ; cols (lane&3)*4+i
        uint4 z0, z1;
        z0.x=f2tf(fmaf(eps,o0.x,A0.x)); z0.y=f2tf(fmaf(eps,o0.y,A0.y));
        z0.z=f2tf(fmaf(eps,o0.z,A0.z)); z0.w=f2tf(fmaf(eps,o0.w,A0.w));
        z1.x=f2tf(fmaf(eps,o1.x,A1.x)); z1.y=f2tf(fmaf(eps,o1.y,A1.y));
        z1.z=f2tf(fmaf(eps,o1.z,A1.z)); z1.w=f2tf(fmaf(eps,o1.w,A1.w));
        *(uint4*)(zb + r*20 + q*4)       = z0;
        *(uint4*)(zb + (8+r)*20 + q*4)   = z1;
    }
    __syncwarp();

    // ---- GEMM1: 2 k-steps, 8 n-tiles ----
    float4 C[2][8];
    #pragma unroll
    for (int nd = 0; nd < 2; nd++)
        #pragma unroll
        for (int n = 0; n < 8; n++) {
            float2 bv = *(const float2*)(bia + n*8 + 2*q);
            C[nd][n] = make_float4(bv.x, bv.y, bv.x, bv.y);
        }
    #pragma unroll
    for (int k = 0; k < 2; k++) {
        u32 b0[8], b1[8];
        #pragma unroll
        for (int n = 0; n < 8; n++) {
            b0[n] = Wa[(k*8 + q)*72 + n*8 + r];
            b1[n] = Wa[(k*8 + q + 4)*72 + n*8 + r];
        }
        #pragma unroll
        for (int nd = 0; nd < 2; nd++) {
            const u32* zb = zS + (w*2 + nd)*320;
            u32 a0 = zb[r*20 + k*8 + q];
            u32 a1 = zb[(8+r)*20 + k*8 + q];
            u32 a2 = zb[r*20 + k*8 + q + 4];
            u32 a3 = zb[(8+r)*20 + k*8 + q + 4];
            #pragma unroll
            for (int n = 0; n < 8; n++) mma8(C[nd][n], a0, a1, a2, a3, b0[n], b1[n]);
        }
    }
    __syncwarp();
    // relu + cvt -> t smem (stride 68)
    #pragma unroll
    for (int nd = 0; nd < 2; nd++) {
        u32* tb = tS + (w*2 + nd)*1088;
        #pragma unroll
        for (int n = 0; n < 8; n++) {
            float4 c = C[nd][n];
            uint2 lo = make_uint2(f2tf(fmaxf(c.x,0.f)), f2tf(fmaxf(c.y,0.f)));
            uint2 hi = make_uint2(f2tf(fmaxf(c.z,0.f)), f2tf(fmaxf(c.w,0.f)));
            *(uint2*)(tb + r*68 + n*8 + 2*q)     = lo;
            *(uint2*)(tb + (8+r)*68 + n*8 + 2*q) = hi;
        }
    }
    __syncwarp();

    // ---- GEMM2: 8 k-steps ----
    #pragma unroll
    for (int nd = 0; nd < 2; nd++)
        #pragma unroll
        for (int n = 0; n < 8; n++) {
            float2 bv = *(const float2*)(bib + n*8 + 2*q);
            C[nd][n] = make_float4(bv.x, bv.y, bv.x, bv.y);
        }
    #pragma unroll
    for (int k = 0; k < 8; k++) {
        u32 b0[8], b1[8];
        #pragma unroll
        for (int n = 0; n < 8; n++) {
            b0[n] = Wb[(k*8 + q)*72 + n*8 + r];
            b1[n] = Wb[(k*8 + q + 4)*72 + n*8 + r];
        }
        #pragma unroll
        for (int nd = 0; nd < 2; nd++) {
            const u32* tb = tS + (w*2 + nd)*1088;
            u32 a0 = tb[r*68 + k*8 + q];
            u32 a1 = tb[(8+r)*68 + k*8 + q];
            u32 a2 = tb[r*68 + k*8 + q + 4];
            u32 a3 = tb[(8+r)*68 + k*8 + q + 4];
            #pragma unroll
            for (int n = 0; n < 8; n++) mma8(C[nd][n], a0, a1, a2, a3, b0[n], b1[n]);
        }
    }
    // relu -> h1 (fp32, [m][d])
    #pragma unroll
    for (int nd = 0; nd < 2; nd++) {
        float* o = g_h1 + (size_t)(vb + nd)*1024;
        #pragma unroll
        for (int n = 0; n < 8; n++) {
            float4 c = C[nd][n];
            *(float2*)(o + r*64 + n*8 + 2*q)     = make_float2(fmaxf(c.x,0.f), fmaxf(c.y,0.f));
            *(float2*)(o + (8+r)*64 + n*8 + 2*q) = make_float2(fmaxf(c.z,0.f), fmaxf(c.w,0.f));
        }
    }
}

// ================= Kernel D: GIN layer 2 + sample-sum (tf32 mma) ===========
__global__ __launch_bounds__(256, 2) void kGin2(
    const float* __restrict__ eps2p,
    const float* __restrict__ W2a, const float* __restrict__ b2a,
    const float* __restrict__ W2b, const float* __restrict__ b2b,
    float* __restrict__ out)
{
    extern __shared__ u32 sh2[];
    u32*   Wa  = sh2;                 // 64*72 = 4608
    u32*   Wb  = Wa + 4608;           // 4608
    float* bia = (float*)(Wb + 4608); // 64
    float* bib = bia + 64;            // 64
    u32*   zS  = (u32*)(bib + 64);    // 16 nodes * 16*68 = 17408 u32 (z then t)

    const int tid = threadIdx.x;
    for (int i = tid; i < 4096; i += 256) {
        int c = i >> 6, d = i & 63;
        Wa[c*72 + d] = f2tf(W2a[i]);
        Wb[c*72 + d] = f2tf(W2b[i]);
    }
    if (tid < 64) { bia[tid] = b2a[tid]; bib[tid] = b2b[tid]; }
    __syncthreads();

    const int lane = tid & 31, w = tid >> 5;
    const int q = lane & 3, r = lane >> 2;
    const int vb = blockIdx.x*16 + w*2;
    const float eps = 1.0f + eps2p[0];

    // ---- aggregation (fp32) -> z smem (tf32), stride 68 ----
    #pragma unroll
    for (int nd = 0; nd < 2; nd++) {
        const int v = vb + nd;
        u32* zb = zS + (w*2 + nd)*1088;
        float4 A[8];
        #pragma unroll
        for (int j = 0; j < 8; j++) A[j] = make_float4(0.f,0.f,0.f,0.f);
        const int cnt = min(g_cnt[v], CAP);
        const int* adj = g_adj + v*CAP;
        for (int e = 0; e < cnt; e++) {
            const float* src = g_h1 + (size_t)adj[e]*1024 + lane*4;
            #pragma unroll
            for (int j = 0; j < 8; j++) {
                float4 x = *(const float4*)(src + j*128);
                A[j].x+=x.x; A[j].y+=x.y; A[j].z+=x.z; A[j].w+=x.w;
            }
        }
        const float* own = g_h1 + (size_t)v*1024 + lane*4;
        #pragma unroll
        for (int j = 0; j < 8; j++) {
            float4 o = *(const float4*)(own + j*128);
            uint4 z;
            z.x = f2tf(fmaf(eps,o.x,A[j].x)); z.y = f2tf(fmaf(eps,o.y,A[j].y));
            z.z = f2tf(fmaf(eps,o.z,A[j].z)); z.w = f2tf(fmaf(eps,o.w,A[j].w));
            int m = 2*j + (lane >> 4), d0 = (lane & 15)*4;
            *(uint4*)(zb + m*68 + d0) = z;
        }
    }
    __syncwarp();

    float4 C[2][8];
    // ---- GEMM1: z @ W2a + b2a, relu ----
    #pragma unroll
    for (int nd = 0; nd < 2; nd++)
        #pragma unroll
        for (int n = 0; n < 8; n++) {
            float2 bv = *(const float2*)(bia + n*8 + 2*q);
            C[nd][n] = make_float4(bv.x, bv.y, bv.x, bv.y);
        }
    #pragma unroll
    for (int k = 0; k < 8; k++) {
        u32 b0[8], b1[8];
        #pragma unroll
        for (int n = 0; n < 8; n++) {
            b0[n] = Wa[(k*8 + q)*72 + n*8 + r];
            b1[n] = Wa[(k*8 + q + 4)*72 + n*8 + r];
        }
        #pragma unroll
        for (int nd = 0; nd < 2; nd++) {
            const u32* zb = zS + (w*2 + nd)*1088;
            u32 a0 = zb[r*68 + k*8 + q];
            u32 a1 = zb[(8+r)*68 + k*8 + q];
            u32 a2 = zb[r*68 + k*8 + q + 4];
            u32 a3 = zb[(8+r)*68 + k*8 + q + 4];
            #pragma unroll
            for (int n = 0; n < 8; n++) mma8(C[nd][n], a0, a1, a2, a3, b0[n], b1[n]);
        }
    }
    __syncwarp();
    // relu + cvt -> overwrite z buffer as t
    #pragma unroll
    for (int nd = 0; nd < 2; nd++) {
        u32* tb = zS + (w*2 + nd)*1088;
        #pragma unroll
        for (int n = 0; n < 8; n++) {
            float4 c = C[nd][n];
            uint2 lo = make_uint2(f2tf(fmaxf(c.x,0.f)), f2tf(fmaxf(c.y,0.f)));
            uint2 hi = make_uint2(f2tf(fmaxf(c.z,0.f)), f2tf(fmaxf(c.w,0.f)));
            *(uint2*)(tb + r*68 + n*8 + 2*q)     = lo;
            *(uint2*)(tb + (8+r)*68 + n*8 + 2*q) = hi;
        }
    }
    __syncwarp();

    // ---- GEMM2: t @ W2b + b2b, relu, sum over m ----
    #pragma unroll
    for (int nd = 0; nd < 2; nd++)
        #pragma unroll
        for (int n = 0; n < 8; n++) {
            float2 bv = *(const float2*)(bib + n*8 + 2*q);
            C[nd][n] = make_float4(bv.x, bv.y, bv.x, bv.y);
        }
    #pragma unroll
    for (int k = 0; k < 8; k++) {
        u32 b0[8], b1[8];
        #pragma unroll
        for (int n = 0; n < 8; n++) {
            b0[n] = Wb[(k*8 + q)*72 + n*8 + r];
            b1[n] = Wb[(k*8 + q + 4)*72 + n*8 + r];
        }
        #pragma unroll
        for (int nd = 0; nd < 2; nd++) {
            const u32* tb = zS + (w*2 + nd)*1088;
            u32 a0 = tb[r*68 + k*8 + q];
            u32 a1 = tb[(8+r)*68 + k*8 + q];
            u32 a2 = tb[r*68 + k*8 + q + 4];
            u32 a3 = tb[(8+r)*68 + k*8 + q + 4];
            #pragma unroll
            for (int n = 0; n < 8; n++) mma8(C[nd][n], a0, a1, a2, a3, b0[n], b1[n]);
        }
    }
    #pragma unroll
    for (int nd = 0; nd < 2; nd++) {
        float s0[8], s1[8];
        #pragma unroll
        for (int n = 0; n < 8; n++) {
            float4 c = C[nd][n];
            s0[n] = fmaxf(c.x,0.f) + fmaxf(c.z,0.f);   // cols 2q
            s1[n] = fmaxf(c.y,0.f) + fmaxf(c.w,0.f);   // cols 2q+1
        }
        #pragma unroll
        for (int o = 4; o < 32; o <<= 1)
            #pragma unroll
            for (int n = 0; n < 8; n++) {
                s0[n] += __shfl_xor_sync(0xffffffffu, s0[n], o);
                s1[n] += __shfl_xor_sync(0xffffffffu, s1[n], o);
            }
        if (lane < 4) {
            float* op = out + (size_t)(vb + nd)*64;
            #pragma unroll
            for (int n = 0; n < 8; n++)
                *(float2*)(op + n*8 + 2*lane) = make_float2(s0[n], s1[n]);
        }
    }
}

// ================= launch ==================================================
extern "C" void kernel_launch(void* const* d_in, const int* in_sizes, int n_in,
                              void* d_out, int out_size)
{
    const float* lap  = (const float*)d_in[0];
    const float* W0   = (const float*)d_in[1];
    const float* mlpW = (const float*)d_in[2];
    const float* mlpb = (const float*)d_in[3];
    const float* bng  = (const float*)d_in[4];
    const float* bnb  = (const float*)d_in[5];
    const float* eps1 = (const float*)d_in[6];
    const float* W1a  = (const float*)d_in[7];
    const float* b1a  = (const float*)d_in[8];
    const float* W1b  = (const float*)d_in[9];
    const float* b1b  = (const float*)d_in[10];
    const float* eps2 = (const float*)d_in[11];
    const float* W2a  = (const float*)d_in[12];
    const float* b2a  = (const float*)d_in[13];
    const float* W2b  = (const float*)d_in[14];
    const float* b2b  = (const float*)d_in[15];
    const int*   ei   = (const int*)d_in[16];
    float* out = (float*)d_out;

    const int SMEM_A  = 21696 * 4;                                   // 86784 B
    const int SMEM_G1 = (1152 + 4608 + 128 + 5120 + 17408) * 4;      // 113664 B
    const int SMEM_G2 = (4608 + 4608 + 128 + 17408) * 4;             // 107008 B
    cudaFuncSetAttribute(kA,    cudaFuncAttributeMaxDynamicSharedMemorySize, SMEM_A);
    cudaFuncSetAttribute(kGin1, cudaFuncAttributeMaxDynamicSharedMemorySize, SMEM_G1);
    cudaFuncSetAttribute(kGin2, cudaFuncAttributeMaxDynamicSharedMemorySize, SMEM_G2);

    kZero<<<NSUM/256, 256>>>();
    kFill<<<NE/256, 256>>>(ei);
    kA   <<<BG, 512, SMEM_A>>>(lap, W0, mlpW, mlpb, bng, bnb);
    kGin1<<<NSUM/16, 256, SMEM_G1>>>(eps1, W1a, b1a, W1b, b1b);
    kGin2<<<NSUM/16, 256, SMEM_G2>>>(eps2, W2a, b2a, W2b, b2b, out);
}